// round 1
// baseline (speedup 1.0000x reference)
#include <cuda_runtime.h>
#include <math.h>

// PDHG / Chambolle-Pock TV denoising, persistent-kernel formulation.
// Shapes: P=2, C=1, NX=128, NY=128, NT=8; T=128 iterations.
// One thread owns one (p,x,y) pencil of all NT=8 t-values.
// x0, p, q2 (t-direction dual), xnoisy, lambda live purely in registers.
// xbar, q0, q1 are double-buffered in __device__ globals for halo exchange.
// One software grid barrier per iteration (128 CTAs <= 148 SMs -> co-resident).

#define NXD 128
#define NYD 128
#define NTD 8
#define NPB 2
#define NPIX (NPB * NXD * NYD * NTD)   // 262144
#define NCTA 128
#define NTHR 256

__device__ float g_xbar[2][NPIX];
__device__ float g_q0[2][NPIX];
__device__ float g_q1[2][NPIX];
__device__ unsigned g_cnt;    // arrival counter (returns to 0 each epoch)
__device__ unsigned g_flag;   // monotonically increasing release epoch

#define LOADP(dst, ptr, off) do { \
    float4 a_ = *reinterpret_cast<const float4*>((ptr) + (off)); \
    float4 b_ = *reinterpret_cast<const float4*>((ptr) + (off) + 4); \
    dst[0]=a_.x; dst[1]=a_.y; dst[2]=a_.z; dst[3]=a_.w; \
    dst[4]=b_.x; dst[5]=b_.y; dst[6]=b_.z; dst[7]=b_.w; } while(0)

#define STOREP(ptr, off, src) do { \
    *reinterpret_cast<float4*>((ptr) + (off))     = make_float4(src[0],src[1],src[2],src[3]); \
    *reinterpret_cast<float4*>((ptr) + (off) + 4) = make_float4(src[4],src[5],src[6],src[7]); } while(0)

// Grid-wide barrier. Caller guarantees all NCTA CTAs are co-resident.
// Release: all threads __threadfence() (stores visible at L2) before arrival.
// Acquire: tid0 spins on g_flag, then __threadfence() (CCTL.IVALL -> fresh L1).
__device__ __forceinline__ void grid_barrier(unsigned& epoch) {
    __threadfence();
    __syncthreads();
    if (threadIdx.x == 0) {
        unsigned old = atomicAdd(&g_cnt, 1u);
        if (old == NCTA - 1u) {
            // Last arriver: everyone is here; reset counter, then release.
            atomicExch(&g_cnt, 0u);
            __threadfence();
            atomicExch(&g_flag, epoch + 1u);
        } else {
            while (atomicAdd(&g_flag, 0u) != epoch + 1u) {
                __nanosleep(32);
            }
        }
        __threadfence();   // acquire side: invalidate L1 for fresh neighbor data
        epoch = epoch + 1u;
    }
    __syncthreads();
}

extern "C" __global__ void __launch_bounds__(NTHR, 1)
pdhg_persist_kernel(const float* __restrict__ xin,
                    const float* __restrict__ lamin,
                    const float* __restrict__ taup,
                    const float* __restrict__ sigp,
                    const float* __restrict__ thp,
                    const int*   __restrict__ Tp,
                    float* __restrict__ out)
{
    // ---- scalars ----
    const float L    = sqrtf(13.0f);
    const float sig  = (1.0f / (1.0f + expf(-sigp[0]))) / L;
    const float tauv = (1.0f / (1.0f + expf(-taup[0]))) / L;
    const float th   = 1.0f / (1.0f + expf(-thp[0]));
    const float i1s  = 1.0f / (1.0f + sig);

    int T = Tp[0];
    if (T < 1 || T > 65536) {            // robustness if T arrived as float bits
        float tf = __int_as_float(T);
        T = (int)tf;
        if (T < 1 || T > 65536) T = 128;
    }

    // ---- thread -> pencil mapping: CTA = 16x16 (x,y) tile ----
    const int cta  = blockIdx.x;          // 0..127
    const int pp   = cta >> 6;            // batch 0..1
    const int tile = cta & 63;            // 8x8 tiles of 16x16
    const int x = ((tile >> 3) << 4) + (threadIdx.x >> 4);
    const int y = ((tile & 7)  << 4) + (threadIdx.x & 15);
    const int xp = (x + 1) & 127, xm = (x - 1) & 127;
    const int yp = (y + 1) & 127, ym = (y - 1) & 127;

    const int pb  = pp << 14;                        // 128*128 pencils per batch
    const int o   = (pb + (x  << 7) + y ) << 3;      // own pencil byte-offset/4
    const int opx = (pb + (xp << 7) + y ) << 3;
    const int omx = (pb + (xm << 7) + y ) << 3;
    const int opy = (pb + (x  << 7) + yp) << 3;
    const int omy = (pb + (x  << 7) + ym) << 3;

    // ---- persistent register state ----
    float xn[8], x0[8], pv[8], q0[8], q1[8], q2[8], xb[8], lam[8], lmx[8], lmy[8];
    LOADP(xn,  xin,   o);
    LOADP(lam, lamin, o);
    LOADP(lmx, lamin, omx);
    LOADP(lmy, lamin, omy);
#pragma unroll
    for (int t = 0; t < 8; t++) {
        x0[t] = xn[t]; pv[t] = xn[t]; xb[t] = xn[t];
        q0[t] = 0.0f;  q1[t] = 0.0f;  q2[t] = 0.0f;
    }

    // init shared buffers (buffer 0 is "cur" for iteration 0)
    STOREP(g_xbar[0], o, xb);
    {
        float zz[8] = {0.f,0.f,0.f,0.f,0.f,0.f,0.f,0.f};
        STOREP(g_q0[0], o, zz);
        STOREP(g_q1[0], o, zz);
    }

    unsigned epoch = 0;
    if (threadIdx.x == 0) epoch = atomicAdd(&g_flag, 0u);
    grid_barrier(epoch);

    // ---- main PDHG loop ----
    for (int it = 0; it < T; ++it) {
        const int cur = it & 1;
        const int nxt = cur ^ 1;

        float bpx[8], bmx[8], bpy[8], bmy[8], qa[8], qb[8];
        LOADP(bpx, g_xbar[cur], opx);
        LOADP(bmx, g_xbar[cur], omx);
        LOADP(bpy, g_xbar[cur], opy);
        LOADP(bmy, g_xbar[cur], omy);
        LOADP(qa,  g_q0[cur],   omx);   // q0 state at (x-1, y)
        LOADP(qb,  g_q1[cur],   omy);   // q1 state at (x, y-1)

        // t-direction dual (forward diff, periodic), fully in-register
        float q2n[8];
#pragma unroll
        for (int t = 0; t < 8; t++) {
            float v = q2[t] + sig * (xb[(t + 1) & 7] - xb[t]);
            q2n[t] = fminf(fmaxf(v, -lam[t]), lam[t]);
        }

#pragma unroll
        for (int t = 0; t < 8; t++) {
            // primal-residual prox
            float pn = (pv[t] + sig * (xb[t] - xn[t])) * i1s;

            // own duals (forward differences)
            float v0  = q0[t] + sig * (bpx[t] - xb[t]);
            float q0n = fminf(fmaxf(v0, -lam[t]), lam[t]);
            float v1  = q1[t] + sig * (bpy[t] - xb[t]);
            float q1n = fminf(fmaxf(v1, -lam[t]), lam[t]);

            // redundant recompute of neighbor duals needed for divergence
            float v0m = qa[t] + sig * (xb[t] - bmx[t]);
            float q0m = fminf(fmaxf(v0m, -lmx[t]), lmx[t]);
            float v1m = qb[t] + sig * (xb[t] - bmy[t]);
            float q1m = fminf(fmaxf(v1m, -lmy[t]), lmy[t]);

            // divergence: sum_d q[d](i - e_d) - q[d](i)
            float dv = (q0m - q0n) + (q1m - q1n)
                     + (q2n[(t + 7) & 7] - q2n[t]);

            float x1  = x0[t] - tauv * (pn + dv);
            float xbn = x1 + th * (x1 - x0[t]);

            x0[t] = x1; pv[t] = pn; q0[t] = q0n; q1[t] = q1n; xb[t] = xbn;
        }
#pragma unroll
        for (int t = 0; t < 8; t++) q2[t] = q2n[t];

        if (it != T - 1) {
            STOREP(g_xbar[nxt], o, xb);
            STOREP(g_q0[nxt],   o, q0);
            STOREP(g_q1[nxt],   o, q1);
            grid_barrier(epoch);
        }
    }

    // ---- output: x1 after T steps ----
    STOREP(out, o, x0);
}

extern "C" void kernel_launch(void* const* d_in, const int* in_sizes, int n_in,
                              void* d_out, int out_size) {
    const float* x    = (const float*)d_in[0];
    const float* lam  = (const float*)d_in[1];
    const float* tau  = (const float*)d_in[2];
    const float* sigm = (const float*)d_in[3];
    const float* thet = (const float*)d_in[4];
    const int*   Tp   = (const int*)d_in[5];
    float* out = (float*)d_out;
    pdhg_persist_kernel<<<NCTA, NTHR>>>(x, lam, tau, sigm, thet, Tp, out);
}

// round 3
// speedup vs baseline: 1.3811x; 1.3811x over previous
#include <cuda_runtime.h>
#include <math.h>

// PDHG / Chambolle-Pock TV denoising, persistent-kernel formulation.
// P=2, C=1, NX=128, NY=128, NT=8; T=128 iterations.
// One thread per (p,x,y) pencil of NT=8 t-values; x0,p,q2,xnoisy,lambda in regs.
// xbar,q0,q1 double-buffered in __device__ globals for halo exchange.
// One CG-style release/acquire grid barrier per iteration (128 CTAs co-resident).

#define NXD 128
#define NYD 128
#define NTD 8
#define NPB 2
#define NPIX (NPB * NXD * NYD * NTD)   // 262144
#define NCTA 128
#define NTHR 256

__device__ __align__(256) float g_xbar[2][NPIX];
__device__ __align__(256) float g_q0[2][NPIX];
__device__ __align__(256) float g_q1[2][NPIX];
__device__ unsigned g_cnt;    // monotonic arrival counter
__device__ unsigned g_flag;   // monotonic release epoch

// ---- memory-model primitives ----
__device__ __forceinline__ unsigned atom_add_acqrel_gpu(unsigned* p, unsigned v) {
    unsigned old;
    asm volatile("atom.acq_rel.gpu.global.add.u32 %0, [%1], %2;"
                 : "=r"(old) : "l"(p), "r"(v) : "memory");
    return old;
}
__device__ __forceinline__ void st_release_gpu(unsigned* p, unsigned v) {
    asm volatile("st.release.gpu.global.u32 [%0], %1;" :: "l"(p), "r"(v) : "memory");
}
__device__ __forceinline__ unsigned ld_acquire_gpu(unsigned* p) {
    unsigned v;
    asm volatile("ld.acquire.gpu.global.u32 %0, [%1];" : "=r"(v) : "l"(p) : "memory");
    return v;
}

// Halo loads: L2-only (.cg) -> never sees stale L1, no CCTL.IVALL needed.
#define LOADP_CG(dst, ptr, off) do { \
    float4 a_ = __ldcg(reinterpret_cast<const float4*>((ptr) + (off))); \
    float4 b_ = __ldcg(reinterpret_cast<const float4*>((ptr) + (off) + 4)); \
    dst[0]=a_.x; dst[1]=a_.y; dst[2]=a_.z; dst[3]=a_.w; \
    dst[4]=b_.x; dst[5]=b_.y; dst[6]=b_.z; dst[7]=b_.w; } while(0)

#define LOADP(dst, ptr, off) do { \
    float4 a_ = *reinterpret_cast<const float4*>((ptr) + (off)); \
    float4 b_ = *reinterpret_cast<const float4*>((ptr) + (off) + 4); \
    dst[0]=a_.x; dst[1]=a_.y; dst[2]=a_.z; dst[3]=a_.w; \
    dst[4]=b_.x; dst[5]=b_.y; dst[6]=b_.z; dst[7]=b_.w; } while(0)

#define STOREP(ptr, off, src) do { \
    *reinterpret_cast<float4*>((ptr) + (off))     = make_float4(src[0],src[1],src[2],src[3]); \
    *reinterpret_cast<float4*>((ptr) + (off) + 4) = make_float4(src[4],src[5],src[6],src[7]); } while(0)

// CG-style grid barrier. base = g_flag value at kernel entry (monotonic across
// harness replays; invariant g_cnt == g_flag*NCTA at quiescence). e = 1..T.
// __syncthreads() + release-atomic cumulativity orders ALL CTA threads' prior
// global stores at gpu scope; ld.acquire gives the matching acquire.
__device__ __forceinline__ void grid_barrier(unsigned base, unsigned e) {
    __syncthreads();
    if (threadIdx.x == 0) {
        unsigned old = atom_add_acqrel_gpu(&g_cnt, 1u);
        if (old - base * NCTA == e * NCTA - 1u) {
            st_release_gpu(&g_flag, base + e);     // last arriver releases
        } else {
            while (ld_acquire_gpu(&g_flag) - base < e) { }   // pure load spin
        }
    }
    __syncthreads();
}

extern "C" __global__ void __launch_bounds__(NTHR, 1)
pdhg_persist_kernel(const float* __restrict__ xin,
                    const float* __restrict__ lamin,
                    const float* __restrict__ taup,
                    const float* __restrict__ sigp,
                    const float* __restrict__ thp,
                    const int*   __restrict__ Tp,
                    float* __restrict__ out)
{
    // ---- scalars ----
    const float L    = sqrtf(13.0f);
    const float sig  = (1.0f / (1.0f + expf(-sigp[0]))) / L;
    const float tauv = (1.0f / (1.0f + expf(-taup[0]))) / L;
    const float th   = 1.0f / (1.0f + expf(-thp[0]));
    const float i1s  = 1.0f / (1.0f + sig);

    int T = Tp[0];
    if (T < 1 || T > 65536) {
        float tf = __int_as_float(T);
        T = (int)tf;
        if (T < 1 || T > 65536) T = 128;
    }

    // ---- thread -> pencil mapping: CTA = 16x16 (x,y) tile ----
    const int cta  = blockIdx.x;          // 0..127
    const int pp   = cta >> 6;            // batch 0..1
    const int tile = cta & 63;            // 8x8 tiles of 16x16
    const int x = ((tile >> 3) << 4) + (threadIdx.x >> 4);
    const int y = ((tile & 7)  << 4) + (threadIdx.x & 15);
    const int xp = (x + 1) & 127, xm = (x - 1) & 127;
    const int yp = (y + 1) & 127, ym = (y - 1) & 127;

    const int pb  = pp << 14;
    const int o   = (pb + (x  << 7) + y ) << 3;
    const int opx = (pb + (xp << 7) + y ) << 3;
    const int omx = (pb + (xm << 7) + y ) << 3;
    const int opy = (pb + (x  << 7) + yp) << 3;
    const int omy = (pb + (x  << 7) + ym) << 3;

    // barrier base epoch (read before anyone can possibly release epoch base+1:
    // a release requires all CTAs to have arrived, hence to have read base)
    unsigned base = 0;
    if (threadIdx.x == 0) base = ld_acquire_gpu(&g_flag);

    // ---- persistent register state ----
    float xn[8], x0[8], pv[8], q0[8], q1[8], q2[8], xb[8], lam[8], lmx[8], lmy[8];
    LOADP(xn,  xin,   o);
    LOADP(lam, lamin, o);
    LOADP(lmx, lamin, omx);
    LOADP(lmy, lamin, omy);
#pragma unroll
    for (int t = 0; t < 8; t++) {
        x0[t] = xn[t]; pv[t] = xn[t]; xb[t] = xn[t];
        q0[t] = 0.0f;  q1[t] = 0.0f;  q2[t] = 0.0f;
    }

    // init shared buffers (buffer 0 is "cur" for iteration 0)
    STOREP(g_xbar[0], o, xb);
    {
        float zz[8] = {0.f,0.f,0.f,0.f,0.f,0.f,0.f,0.f};
        STOREP(g_q0[0], o, zz);
        STOREP(g_q1[0], o, zz);
    }

    grid_barrier(base, 1);

    // ---- main PDHG loop ----
    for (int it = 0; it < T; ++it) {
        const int cur = it & 1;
        const int nxt = cur ^ 1;

        // front-batch all halo loads (MLP), .cg = fresh from L2
        float bpx[8], bmx[8], bpy[8], bmy[8], qa[8], qb[8];
        LOADP_CG(bpx, g_xbar[cur], opx);
        LOADP_CG(bmx, g_xbar[cur], omx);
        LOADP_CG(bpy, g_xbar[cur], opy);
        LOADP_CG(bmy, g_xbar[cur], omy);
        LOADP_CG(qa,  g_q0[cur],   omx);   // q0 state at (x-1, y)
        LOADP_CG(qb,  g_q1[cur],   omy);   // q1 state at (x, y-1)

        // t-direction dual (periodic fwd diff) — independent of halo loads,
        // overlaps with their L2 latency
        float q2n[8];
#pragma unroll
        for (int t = 0; t < 8; t++) {
            float v = q2[t] + sig * (xb[(t + 1) & 7] - xb[t]);
            q2n[t] = fminf(fmaxf(v, -lam[t]), lam[t]);
        }

#pragma unroll
        for (int t = 0; t < 8; t++) {
            float pn = (pv[t] + sig * (xb[t] - xn[t])) * i1s;

            float v0  = q0[t] + sig * (bpx[t] - xb[t]);
            float q0n = fminf(fmaxf(v0, -lam[t]), lam[t]);
            float v1  = q1[t] + sig * (bpy[t] - xb[t]);
            float q1n = fminf(fmaxf(v1, -lam[t]), lam[t]);

            // redundant recompute of neighbor duals for the divergence
            float v0m = qa[t] + sig * (xb[t] - bmx[t]);
            float q0m = fminf(fmaxf(v0m, -lmx[t]), lmx[t]);
            float v1m = qb[t] + sig * (xb[t] - bmy[t]);
            float q1m = fminf(fmaxf(v1m, -lmy[t]), lmy[t]);

            float dv = (q0m - q0n) + (q1m - q1n)
                     + (q2n[(t + 7) & 7] - q2n[t]);

            float x1  = x0[t] - tauv * (pn + dv);
            float xbn = x1 + th * (x1 - x0[t]);

            x0[t] = x1; pv[t] = pn; q0[t] = q0n; q1[t] = q1n; xb[t] = xbn;
        }
#pragma unroll
        for (int t = 0; t < 8; t++) q2[t] = q2n[t];

        if (it != T - 1) {
            STOREP(g_xbar[nxt], o, xb);
            STOREP(g_q0[nxt],   o, q0);
            STOREP(g_q1[nxt],   o, q1);
            grid_barrier(base, it + 2);
        }
    }

    // ---- output ----
    STOREP(out, o, x0);
}

extern "C" void kernel_launch(void* const* d_in, const int* in_sizes, int n_in,
                              void* d_out, int out_size) {
    const float* x    = (const float*)d_in[0];
    const float* lam  = (const float*)d_in[1];
    const float* tau  = (const float*)d_in[2];
    const float* sigm = (const float*)d_in[3];
    const float* thet = (const float*)d_in[4];
    const int*   Tp   = (const int*)d_in[5];
    float* out = (float*)d_out;
    pdhg_persist_kernel<<<NCTA, NTHR>>>(x, lam, sigm ? tau : tau, sigm, thet, Tp, out);
}